// round 11
// baseline (speedup 1.0000x reference)
#include <cuda_runtime.h>
#include <cuda_fp16.h>
#include <cstdint>
#include <cstddef>

#define DI __device__ __forceinline__

static constexpr int M_TOT = 8192, N_TOT = 4096, K_TOT = 4096;
static constexpr int BM = 128, BN = 128, BK = 64;
static constexpr int NSTG = 3;
static constexpr int NK = K_TOT / BK;                 // 64 chunks

static constexpr int A_STG = BM * 128;                // 16384 B
static constexpr int B_STG = BN * 128;                // 16384 B
static constexpr int STAGE_BYTES = A_STG + B_STG;     // 32768 B
static constexpr int SM_BIAS = 0;                     // 128 floats
static constexpr int SM_STAGE = 1024;
static constexpr int SMEM_TOTAL = SM_STAGE + NSTG * STAGE_BYTES;  // 99328; x2 CTAs fits 227KB

// scratch (allocation-free rule: __device__ globals)
__device__ uint4 g_x16_v[(size_t)M_TOT * K_TOT / 8];   // 64 MB fp16 x
__device__ uint4 g_w16_v[(size_t)N_TOT * K_TOT / 8];   // 32 MB fp16 W

// ------------------------- PTX helpers (sm_80+ baseline only) -------------------------
DI uint32_t smem_u32(const void* p) {
    uint32_t a;
    asm("{.reg .u64 t; cvta.to.shared.u64 t, %1; cvt.u32.u64 %0, t;}" : "=r"(a) : "l"(p));
    return a;
}
DI void cp16(uint32_t dst, const void* src) {
    asm volatile("cp.async.cg.shared.global [%0], [%1], 16;" :: "r"(dst), "l"(src));
}
DI void cp_commit() { asm volatile("cp.async.commit_group;" ::: "memory"); }
template <int N> DI void cp_wait() { asm volatile("cp.async.wait_group %0;" :: "n"(N) : "memory"); }

DI void ldsm_x4(uint32_t& r0, uint32_t& r1, uint32_t& r2, uint32_t& r3, uint32_t a) {
    asm volatile("ldmatrix.sync.aligned.m8n8.x4.shared.b16 {%0,%1,%2,%3}, [%4];"
                 : "=r"(r0), "=r"(r1), "=r"(r2), "=r"(r3) : "r"(a));
}
DI void mma16816(float* c, uint32_t a0, uint32_t a1, uint32_t a2, uint32_t a3,
                 uint32_t b0, uint32_t b1) {
    asm volatile(
        "mma.sync.aligned.m16n8k16.row.col.f32.f16.f16.f32 "
        "{%0,%1,%2,%3}, {%4,%5,%6,%7}, {%8,%9}, {%0,%1,%2,%3};"
        : "+f"(c[0]), "+f"(c[1]), "+f"(c[2]), "+f"(c[3])
        : "r"(a0), "r"(a1), "r"(a2), "r"(a3), "r"(b0), "r"(b1));
}
#define SWZ(row, colbyte) ((uint32_t)(colbyte) ^ (((uint32_t)(row) & 7u) << 4))

// ------------------- fused pre-kernel: x fp32->fp16  +  fp4 dequant ------------------
DI float fp4_val(uint32_t n) {
    uint32_t s = (n >> 3) & 1, e = (n >> 1) & 3, m = n & 1;
    uint32_t bits = e ? (((e + 126u) << 23) | (m << 22)) : (m ? 0x3F000000u : 0u);
    bits |= s << 31;
    return __uint_as_float(bits);
}

static constexpr int CVT_BLOCKS = (M_TOT * K_TOT / 8) / 256;   // 16384

__global__ void __launch_bounds__(256) prep_kernel(const float4* __restrict__ x,
                                                   const int* __restrict__ wd,
                                                   const int* __restrict__ ws,
                                                   const float* __restrict__ g) {
    if (blockIdx.x < CVT_BLOCKS) {
        size_t i = (size_t)blockIdx.x * 256 + threadIdx.x;   // 8 floats per thread
        float4 a = x[2 * i], b = x[2 * i + 1];
        __half2* o = (__half2*)g_x16_v;
        o[4 * i + 0] = __floats2half2_rn(a.x, a.y);
        o[4 * i + 1] = __floats2half2_rn(a.z, a.w);
        o[4 * i + 2] = __floats2half2_rn(b.x, b.y);
        o[4 * i + 3] = __floats2half2_rn(b.z, b.w);
    } else {
        int row = blockIdx.x - CVT_BLOCKS;   // 0..4095
        int grp = threadIdx.x;               // 0..255
        float gl = *g;
        int code = ws[row * 256 + grp];
        int e = (code >> 3) & 0xF, mm = code & 7;
        float sc = e ? __uint_as_float(((uint32_t)(e + 120) << 23) | ((uint32_t)mm << 20))
                     : (float)mm * 0.001953125f;
        if (code & 0x80) sc = -sc;
        sc *= gl;

        const int4* src = (const int4*)(wd + (size_t)row * 2048 + grp * 8);
        int4 p0 = src[0], p1 = src[1];
        int v[8] = {p0.x, p0.y, p0.z, p0.w, p1.x, p1.y, p1.z, p1.w};
        __half2 o[8];
#pragma unroll
        for (int j = 0; j < 8; ++j) {
            uint32_t b = (uint32_t)v[j];
            o[j] = __floats2half2_rn(fp4_val(b & 0xF) * sc, fp4_val((b >> 4) & 0xF) * sc);
        }
        uint4* dst = (uint4*)((half*)g_w16_v + (size_t)row * 4096 + grp * 16);
        dst[0] = ((const uint4*)o)[0];
        dst[1] = ((const uint4*)o)[1];
    }
}

// -- GEMM: mma.sync f16, 128x128 tile, 4 warps (64x64), cross-chunk pipelined, 2 CTA/SM --
__global__ void __launch_bounds__(128, 2) gemm_kernel(const float* __restrict__ bias,
                                                      float* __restrict__ out) {
    extern __shared__ char smem[];
    const uint32_t sb = smem_u32(smem);
    const int tid = threadIdx.x, wid = tid >> 5, lane = tid & 31;
    const int wm = wid >> 1;          // 0..1  -> 64-row band
    const int wn = wid & 1;           // 0..1  -> 64-col band
    const int n0 = blockIdx.x * BN;
    const int m0 = blockIdx.y * BM;
    const half* X = (const half*)g_x16_v;
    const half* Wm = (const half*)g_w16_v;

    ((float*)(smem + SM_BIAS))[tid] = bias[n0 + tid];

    const int a_row_l = (lane & 15);
    const int a_col_l = ((lane >> 4) << 3) * 2;
    const int b_row_l = ((lane >> 4) << 3) + (lane & 7);
    const int b_col_l = (((lane >> 3) & 1) << 3) * 2;

    auto load_stage = [&](int chunk) {
        const uint32_t st = sb + SM_STAGE + (uint32_t)(chunk % NSTG) * STAGE_BYTES;
        const int kc = chunk * BK;
#pragma unroll
        for (int j = 0; j < 16; ++j) {
            int c = tid + 128 * j;
            int row = c >> 3, col = c & 7;
            int isA = (row < BM);
            int lr = isA ? row : row - BM;
            const half* src = isA ? (X + (size_t)(m0 + lr) * K_TOT + kc + col * 8)
                                  : (Wm + (size_t)(n0 + lr) * K_TOT + kc + col * 8);
            uint32_t dst = st + (isA ? 0u : (uint32_t)A_STG)
                              + (uint32_t)lr * 128 + SWZ(lr, col * 16);
            cp16(dst, src);
        }
    };

    auto load_frags = [&](int chunk, int ks, uint32_t (*af)[4], uint32_t (*bfr)[2]) {
        const uint32_t st = sb + SM_STAGE + (uint32_t)(chunk % NSTG) * STAGE_BYTES;
        const uint32_t aS = st, bS = st + A_STG;
        const int k0b = ks * 32;
#pragma unroll
        for (int mi = 0; mi < 4; ++mi) {               // A frags (rows = m)
            int row = wm * 64 + mi * 16 + a_row_l;
            ldsm_x4(af[mi][0], af[mi][1], af[mi][2], af[mi][3],
                    aS + (uint32_t)row * 128 + SWZ(row, k0b + a_col_l));
        }
#pragma unroll
        for (int p = 0; p < 4; ++p) {                  // B frags: NON-trans (rows = n)
            int row = wn * 64 + p * 16 + b_row_l;
            ldsm_x4(bfr[2 * p][0], bfr[2 * p][1], bfr[2 * p + 1][0], bfr[2 * p + 1][1],
                    bS + (uint32_t)row * 128 + SWZ(row, k0b + b_col_l));
        }
    };

    float acc[4][8][4];
#pragma unroll
    for (int mi = 0; mi < 4; ++mi)
#pragma unroll
        for (int ni = 0; ni < 8; ++ni)
#pragma unroll
            for (int q = 0; q < 4; ++q) acc[mi][ni][q] = 0.f;

    uint32_t af[2][4][4], bf[2][8][2];

    // prologue: stages 0,1 in flight; stage0 ready; frags(0,0) in buf0
    load_stage(0); cp_commit();
    load_stage(1); cp_commit();
    cp_wait<1>();
    __syncthreads();
    load_frags(0, 0, af[0], bf[0]);

#define MMA_BLOCK(BUF)                                                              \
    _Pragma("unroll")                                                               \
    for (int mi = 0; mi < 4; ++mi)                                                  \
        _Pragma("unroll")                                                           \
        for (int ni = 0; ni < 8; ++ni)                                              \
            mma16816(acc[mi][ni], af[BUF][mi][0], af[BUF][mi][1],                   \
                     af[BUF][mi][2], af[BUF][mi][3], bf[BUF][ni][0], bf[BUF][ni][1])

#pragma unroll 1
    for (int ki = 0; ki < NK; ++ki) {
        // barrier: all warps done reading stage (ki-1) frags; writes to its alias follow
        __syncthreads();
        if (ki + 2 < NK) load_stage(ki + 2);
        cp_commit();                                   // commit (possibly empty) group

        // ks 0: consume buf0=(ki,0), load buf1=(ki,1)
        load_frags(ki, 1, af[1], bf[1]);
        MMA_BLOCK(0);
        // ks 1: consume buf1, load buf0=(ki,2)
        load_frags(ki, 2, af[0], bf[0]);
        MMA_BLOCK(1);
        // ks 2: stage ki+1 guaranteed after this wait (issued a full chunk ago)
        cp_wait<1>();
        load_frags(ki, 3, af[1], bf[1]);
        MMA_BLOCK(0);
        // ks 3: prefetch next chunk's first frags BEFORE the barrier
        if (ki + 1 < NK) load_frags(ki + 1, 0, af[0], bf[0]);
        MMA_BLOCK(1);
    }
    cp_wait<0>();

    // epilogue: D m16n8 frag layout -> global + bias
    const float* sbias = (const float*)(smem + SM_BIAS);
#pragma unroll
    for (int mi = 0; mi < 4; ++mi) {
        int mr = m0 + wm * 64 + mi * 16 + (lane >> 2);
        float* o0 = out + (size_t)mr * N_TOT;
        float* o1 = out + (size_t)(mr + 8) * N_TOT;
#pragma unroll
        for (int ni = 0; ni < 8; ++ni) {
            int nc = wn * 64 + ni * 8 + (lane & 3) * 2;
            float b0 = sbias[nc], b1 = sbias[nc + 1];
            int ng = n0 + nc;
            *(float2*)(o0 + ng) = make_float2(acc[mi][ni][0] + b0, acc[mi][ni][1] + b1);
            *(float2*)(o1 + ng) = make_float2(acc[mi][ni][2] + b0, acc[mi][ni][3] + b1);
        }
    }
}

// ------------------------- launch -------------------------
extern "C" void kernel_launch(void* const* d_in, const int* in_sizes, int n_in,
                              void* d_out, int out_size) {
    const float* x  = (const float*)d_in[0];
    const int* wd   = (const int*)d_in[1];
    const int* ws   = (const int*)d_in[2];
    const float* g  = (const float*)d_in[3];
    const float* bias = (const float*)d_in[4];
    float* out = (float*)d_out;

    prep_kernel<<<CVT_BLOCKS + N_TOT, 256>>>((const float4*)x, wd, ws, g);

    cudaFuncSetAttribute(gemm_kernel, cudaFuncAttributeMaxDynamicSharedMemorySize, SMEM_TOTAL);
    dim3 grid(N_TOT / BN, M_TOT / BM);   // (32, 64)
    gemm_kernel<<<grid, 128, SMEM_TOTAL>>>(bias, out);
}

// round 14
// speedup vs baseline: 1.0071x; 1.0071x over previous
#include <cuda_runtime.h>
#include <cuda_fp16.h>
#include <cstdint>
#include <cstddef>

#define DI __device__ __forceinline__

static constexpr int M_TOT = 8192, N_TOT = 4096, K_TOT = 4096;
static constexpr int BM = 128, BN = 128, BK = 64;
static constexpr int NSTG = 3;
static constexpr int NK = K_TOT / BK;                 // 64 chunks

static constexpr int A_STG = BM * 128;                // 16384 B
static constexpr int B_STG = BN * 128;                // 16384 B
static constexpr int STAGE_BYTES = A_STG + B_STG;     // 32768 B
static constexpr int SM_BIAS = 0;                     // 128 floats = 512 B
static constexpr int SM_MBAR = 512;                   // 3 stages x (full,empty) x 8 B
static constexpr int SM_STAGE = 1024;
static constexpr int SMEM_TOTAL = SM_STAGE + NSTG * STAGE_BYTES;  // 99328; x2 CTAs fits 227KB

// scratch (allocation-free rule: __device__ globals)
__device__ uint4 g_x16_v[(size_t)M_TOT * K_TOT / 8];   // 64 MB fp16 x
__device__ uint4 g_w16_v[(size_t)N_TOT * K_TOT / 8];   // 32 MB fp16 W

// ------------------------- PTX helpers (sm_80/90 baseline only) -------------------------
DI uint32_t smem_u32(const void* p) {
    uint32_t a;
    asm("{.reg .u64 t; cvta.to.shared.u64 t, %1; cvt.u32.u64 %0, t;}" : "=r"(a) : "l"(p));
    return a;
}
DI void cp16(uint32_t dst, const void* src) {
    asm volatile("cp.async.cg.shared.global [%0], [%1], 16;" :: "r"(dst), "l"(src));
}
DI void mbar_init(uint32_t addr, uint32_t count) {
    asm volatile("mbarrier.init.shared.b64 [%0], %1;" :: "r"(addr), "r"(count) : "memory");
}
DI void cp_arrive_noinc(uint32_t mbar) {  // arrive (counted) when this thread's cp.asyncs land
    asm volatile("cp.async.mbarrier.arrive.noinc.shared.b64 [%0];" :: "r"(mbar) : "memory");
}
DI void mbar_arrive(uint32_t mbar) {
    asm volatile("{\n\t.reg .b64 t;\n\tmbarrier.arrive.shared.b64 t, [%0];\n\t}"
                 :: "r"(mbar) : "memory");
}
DI void mbar_wait(uint32_t addr, uint32_t parity) {
    asm volatile(
        "{\n\t.reg .pred P;\n\t"
        "W%=:\n\t"
        "mbarrier.try_wait.parity.shared.b64 P, [%0], %1;\n\t"
        "@!P bra W%=;\n\t"
        "}"
        :: "r"(addr), "r"(parity) : "memory");
}

DI void ldsm_x4(uint32_t& r0, uint32_t& r1, uint32_t& r2, uint32_t& r3, uint32_t a) {
    asm volatile("ldmatrix.sync.aligned.m8n8.x4.shared.b16 {%0,%1,%2,%3}, [%4];"
                 : "=r"(r0), "=r"(r1), "=r"(r2), "=r"(r3) : "r"(a));
}
DI void mma16816(float* c, uint32_t a0, uint32_t a1, uint32_t a2, uint32_t a3,
                 uint32_t b0, uint32_t b1) {
    asm volatile(
        "mma.sync.aligned.m16n8k16.row.col.f32.f16.f16.f32 "
        "{%0,%1,%2,%3}, {%4,%5,%6,%7}, {%8,%9}, {%0,%1,%2,%3};"
        : "+f"(c[0]), "+f"(c[1]), "+f"(c[2]), "+f"(c[3])
        : "r"(a0), "r"(a1), "r"(a2), "r"(a3), "r"(b0), "r"(b1));
}
#define SWZ(row, colbyte) ((uint32_t)(colbyte) ^ (((uint32_t)(row) & 7u) << 4))

// ------------------- fused pre-kernel: x fp32->fp16  +  fp4 dequant ------------------
DI float fp4_val(uint32_t n) {
    uint32_t s = (n >> 3) & 1, e = (n >> 1) & 3, m = n & 1;
    uint32_t bits = e ? (((e + 126u) << 23) | (m << 22)) : (m ? 0x3F000000u : 0u);
    bits |= s << 31;
    return __uint_as_float(bits);
}

static constexpr int CVT_BLOCKS = (M_TOT * K_TOT / 8) / 256;   // 16384

__global__ void __launch_bounds__(256) prep_kernel(const float4* __restrict__ x,
                                                   const int* __restrict__ wd,
                                                   const int* __restrict__ ws,
                                                   const float* __restrict__ g) {
    if (blockIdx.x < CVT_BLOCKS) {
        size_t i = (size_t)blockIdx.x * 256 + threadIdx.x;   // 8 floats per thread
        float4 a = x[2 * i], b = x[2 * i + 1];
        __half2* o = (__half2*)g_x16_v;
        o[4 * i + 0] = __floats2half2_rn(a.x, a.y);
        o[4 * i + 1] = __floats2half2_rn(a.z, a.w);
        o[4 * i + 2] = __floats2half2_rn(b.x, b.y);
        o[4 * i + 3] = __floats2half2_rn(b.z, b.w);
    } else {
        int row = blockIdx.x - CVT_BLOCKS;   // 0..4095
        int grp = threadIdx.x;               // 0..255
        float gl = *g;
        int code = ws[row * 256 + grp];
        int e = (code >> 3) & 0xF, mm = code & 7;
        float sc = e ? __uint_as_float(((uint32_t)(e + 120) << 23) | ((uint32_t)mm << 20))
                     : (float)mm * 0.001953125f;
        if (code & 0x80) sc = -sc;
        sc *= gl;

        const int4* src = (const int4*)(wd + (size_t)row * 2048 + grp * 8);
        int4 p0 = src[0], p1 = src[1];
        int v[8] = {p0.x, p0.y, p0.z, p0.w, p1.x, p1.y, p1.z, p1.w};
        __half2 o[8];
#pragma unroll
        for (int j = 0; j < 8; ++j) {
            uint32_t b = (uint32_t)v[j];
            o[j] = __floats2half2_rn(fp4_val(b & 0xF) * sc, fp4_val((b >> 4) & 0xF) * sc);
        }
        uint4* dst = (uint4*)((half*)g_w16_v + (size_t)row * 4096 + grp * 16);
        dst[0] = ((const uint4*)o)[0];
        dst[1] = ((const uint4*)o)[1];
    }
}

// -- GEMM: mma.sync f16, 128x128 tile, 4 warps (64x64), mbarrier pipeline, 2 CTAs/SM --
__global__ void __launch_bounds__(128, 2) gemm_kernel(const float* __restrict__ bias,
                                                      float* __restrict__ out) {
    extern __shared__ char smem[];
    const uint32_t sb = smem_u32(smem);
    const int tid = threadIdx.x, wid = tid >> 5, lane = tid & 31;
    const int wm = wid >> 1;          // 0..1  -> 64-row band
    const int wn = wid & 1;           // 0..1  -> 64-col band
    const int n0 = blockIdx.x * BN;
    const int m0 = blockIdx.y * BM;
    const half* X = (const half*)g_x16_v;
    const half* Wm = (const half*)g_w16_v;

    ((float*)(smem + SM_BIAS))[tid] = bias[n0 + tid];
    if (tid == 0) {
#pragma unroll
        for (int s = 0; s < NSTG; ++s) {
            mbar_init(sb + SM_MBAR + s * 16, 128);       // full[s]: 128 cp-complete arrivals
            mbar_init(sb + SM_MBAR + s * 16 + 8, 128);   // empty[s]: 128 reader arrivals
        }
    }
    __syncthreads();   // one-time: mbar init + bias visible

    const uint32_t mb = sb + SM_MBAR;
    auto fullb  = [&](int s) { return mb + (uint32_t)s * 16; };
    auto emptyb = [&](int s) { return mb + (uint32_t)s * 16 + 8; };

    // parity bits: [s] = full parity, [8+s] = empty parity (empty starts at 1)
    uint32_t par = 0x7u << 8;

    const int a_row_l = (lane & 15);
    const int a_col_l = ((lane >> 4) << 3) * 2;
    const int b_row_l = ((lane >> 4) << 3) + (lane & 7);
    const int b_col_l = (((lane >> 3) & 1) << 3) * 2;

    auto produce = [&](int chunk) {      // wait empty, issue cp.async, arrive(noinc) full
        const int s = chunk % NSTG;
        mbar_wait(emptyb(s), (par >> (8 + s)) & 1u);
        par ^= 1u << (8 + s);
        const uint32_t st = sb + SM_STAGE + (uint32_t)s * STAGE_BYTES;
        const int kc = chunk * BK;
#pragma unroll
        for (int j = 0; j < 16; ++j) {
            int c = tid + 128 * j;
            int row = c >> 3, col = c & 7;
            int isA = (row < BM);
            int lr = isA ? row : row - BM;
            const half* src = isA ? (X + (size_t)(m0 + lr) * K_TOT + kc + col * 8)
                                  : (Wm + (size_t)(n0 + lr) * K_TOT + kc + col * 8);
            uint32_t dst = st + (isA ? 0u : (uint32_t)A_STG)
                              + (uint32_t)lr * 128 + SWZ(lr, col * 16);
            cp16(dst, src);
        }
        cp_arrive_noinc(fullb(s));       // counted arrive on cp completion (.noinc!)
    };

    auto load_frags = [&](int s, int ks, uint32_t (*af)[4], uint32_t (*bfr)[2]) {
        const uint32_t st = sb + SM_STAGE + (uint32_t)s * STAGE_BYTES;
        const uint32_t aS = st, bS = st + A_STG;
        const int k0b = ks * 32;
#pragma unroll
        for (int mi = 0; mi < 4; ++mi) {               // A frags (rows = m)
            int row = wm * 64 + mi * 16 + a_row_l;
            ldsm_x4(af[mi][0], af[mi][1], af[mi][2], af[mi][3],
                    aS + (uint32_t)row * 128 + SWZ(row, k0b + a_col_l));
        }
#pragma unroll
        for (int p = 0; p < 4; ++p) {                  // B frags: NON-trans (rows = n)
            int row = wn * 64 + p * 16 + b_row_l;
            ldsm_x4(bfr[2 * p][0], bfr[2 * p][1], bfr[2 * p + 1][0], bfr[2 * p + 1][1],
                    bS + (uint32_t)row * 128 + SWZ(row, k0b + b_col_l));
        }
    };

    float acc[4][8][4];
#pragma unroll
    for (int mi = 0; mi < 4; ++mi)
#pragma unroll
        for (int ni = 0; ni < 8; ++ni)
#pragma unroll
            for (int q = 0; q < 4; ++q) acc[mi][ni][q] = 0.f;

    uint32_t af[2][4][4], bf[2][8][2];

#define MMA_BLOCK(BUF)                                                              \
    _Pragma("unroll")                                                               \
    for (int mi = 0; mi < 4; ++mi)                                                  \
        _Pragma("unroll")                                                           \
        for (int ni = 0; ni < 8; ++ni)                                              \
            mma16816(acc[mi][ni], af[BUF][mi][0], af[BUF][mi][1],                   \
                     af[BUF][mi][2], af[BUF][mi][3], bf[BUF][ni][0], bf[BUF][ni][1])

    produce(0);
    produce(1);

#pragma unroll 1
    for (int ki = 0; ki < NK; ++ki) {
        const int s = ki % NSTG;
        mbar_wait(fullb(s), (par >> s) & 1u);
        par ^= 1u << s;

        load_frags(s, 0, af[0], bf[0]);
        load_frags(s, 1, af[1], bf[1]);
        MMA_BLOCK(0);                          // 256+ cyc of tensor work queued
        if (ki + 2 < NK) produce(ki + 2);      // may block on empty — covered by queue
        load_frags(s, 2, af[0], bf[0]);
        MMA_BLOCK(1);
        load_frags(s, 3, af[1], bf[1]);
        MMA_BLOCK(0);
        mbar_arrive(emptyb(s));                // all my reads of stage s done
        MMA_BLOCK(1);
    }

    // epilogue: D m16n8 frag layout -> global + bias
    const float* sbias = (const float*)(smem + SM_BIAS);
#pragma unroll
    for (int mi = 0; mi < 4; ++mi) {
        int mr = m0 + wm * 64 + mi * 16 + (lane >> 2);
        float* o0 = out + (size_t)mr * N_TOT;
        float* o1 = out + (size_t)(mr + 8) * N_TOT;
#pragma unroll
        for (int ni = 0; ni < 8; ++ni) {
            int nc = wn * 64 + ni * 8 + (lane & 3) * 2;
            float b0 = sbias[nc], b1 = sbias[nc + 1];
            int ng = n0 + nc;
            *(float2*)(o0 + ng) = make_float2(acc[mi][ni][0] + b0, acc[mi][ni][1] + b1);
            *(float2*)(o1 + ng) = make_float2(acc[mi][ni][2] + b0, acc[mi][ni][3] + b1);
        }
    }
}

// ------------------------- launch -------------------------
extern "C" void kernel_launch(void* const* d_in, const int* in_sizes, int n_in,
                              void* d_out, int out_size) {
    const float* x  = (const float*)d_in[0];
    const int* wd   = (const int*)d_in[1];
    const int* ws   = (const int*)d_in[2];
    const float* g  = (const float*)d_in[3];
    const float* bias = (const float*)d_in[4];
    float* out = (float*)d_out;

    prep_kernel<<<CVT_BLOCKS + N_TOT, 256>>>((const float4*)x, wd, ws, g);

    cudaFuncSetAttribute(gemm_kernel, cudaFuncAttributeMaxDynamicSharedMemorySize, SMEM_TOTAL);
    dim3 grid(N_TOT / BN, M_TOT / BM);   // (32, 64)
    gemm_kernel<<<grid, 128, SMEM_TOTAL>>>(bias, out);
}